// round 11
// baseline (speedup 1.0000x reference)
#include <cuda_runtime.h>

#define T_STEPS 256
#define NPRE    1024
#define NPOST   1024
#define K       16            // 2^-16 rel truncation; measured rel_err 3.2e-5, 30x under 1e-3
#define ROWS    4             // 256 blocks x 1024 thr, 2 CTAs/SM -> ~90% occupancy
#define NBLK    (NPRE / ROWS) // 256
#define NTHR    1024

// e[i][j] = x[i]*q_last[j] - p_last[i]*y[j]
// x = sum_t pre[t][i] * 2^(t-T)  (TE=1 wipes e history; TP=TN=2 give geometric traces)
__global__ __launch_bounds__(NTHR, 2)
void stdp_fused_kernel(const float* __restrict__ pre,
                       const float* __restrict__ post,
                       float* __restrict__ e) {
    __shared__ float4 s_part[4][NPOST / 4];  // per-k-quarter partial y (float4 cols)
    __shared__ float4 s_q4[NPOST / 4];       // post[T-1][:]
    __shared__ float  sx[ROWS];              // x trace for this block's rows
    __shared__ float  sp[ROWS];              // pre[T-1][block rows]

    const int tid  = threadIdx.x;
    const int col4 = tid & 255;              // float4 column group 0..255
    const int kq   = tid >> 8;               // k-quarter / row selector 0..3

    // ---- Phase A: partial y over 4 timesteps for 4 columns (4x LDG.128) ----
    {
        const float4* __restrict__ b =
            reinterpret_cast<const float4*>(post + (size_t)(T_STEPS - K + kq * 4) * NPOST) + col4;
        const float4 v0 = b[0 * (NPOST / 4)];
        const float4 v1 = b[1 * (NPOST / 4)];
        const float4 v2 = b[2 * (NPOST / 4)];
        const float4 v3 = b[3 * (NPOST / 4)];

        // weight(k) = 2^(k-16) = 2^(4*kq-16) * {1,2,4,8}; exact ldexp via exponent bits
        const float wb = __uint_as_float((unsigned)(127 - K + 4 * kq) << 23);

        float4 s;
        s.x = wb * fmaf(8.0f, v3.x, fmaf(4.0f, v2.x, fmaf(2.0f, v1.x, v0.x)));
        s.y = wb * fmaf(8.0f, v3.y, fmaf(4.0f, v2.y, fmaf(2.0f, v1.y, v0.y)));
        s.z = wb * fmaf(8.0f, v3.z, fmaf(4.0f, v2.z, fmaf(2.0f, v1.z, v0.z)));
        s.w = wb * fmaf(8.0f, v3.w, fmaf(4.0f, v2.w, fmaf(2.0f, v1.w, v0.w)));
        s_part[kq][col4] = s;

        if (kq == 3) s_q4[col4] = v3;        // k = 15 load doubles as q_last
    }

    // ---- Phase B: x[i], p_last[i]; warps 8..11, one warp per row ----
    {
        const int wid  = tid >> 5;
        const int lane = tid & 31;
        if (wid >= 8 && wid < 8 + ROWS) {
            const int r = wid - 8;
            const int i = blockIdx.x * ROWS + r;
            float v = 0.0f;
            if (lane < K) {
                v = pre[(size_t)(T_STEPS - K + lane) * NPRE + i]
                    * __uint_as_float((unsigned)(127 - K + lane) << 23);  // exact 2^(lane-16)
            }
            #pragma unroll
            for (int o = 8; o; o >>= 1) v += __shfl_xor_sync(0xFFFFFFFFu, v, o);
            if (lane == 0)     sx[r] = v;    // lanes 0..15 hold the sum
            if (lane == K - 1) sp[r] = pre[(size_t)(T_STEPS - 1) * NPRE + i];
        }
    }

    __syncthreads();

    // ---- Phase C: sum partials inline, rank-2 outer product, 1x STG.128 ----
    const float4 p0 = s_part[0][col4];
    const float4 p1 = s_part[1][col4];
    const float4 p2 = s_part[2][col4];
    const float4 p3 = s_part[3][col4];
    const float4 q4 = s_q4[col4];

    float4 y4;
    y4.x = (p0.x + p1.x) + (p2.x + p3.x);
    y4.y = (p0.y + p1.y) + (p2.y + p3.y);
    y4.z = (p0.z + p1.z) + (p2.z + p3.z);
    y4.w = (p0.w + p1.w) + (p2.w + p3.w);

    const int   i  = blockIdx.x * ROWS + kq;   // this thread's single output row
    const float xi = sx[kq];
    const float pi = sp[kq];

    float4 o;
    o.x = fmaf(xi, q4.x, -pi * y4.x);
    o.y = fmaf(xi, q4.y, -pi * y4.y);
    o.z = fmaf(xi, q4.z, -pi * y4.z);
    o.w = fmaf(xi, q4.w, -pi * y4.w);

    reinterpret_cast<float4*>(e)[(size_t)i * (NPOST / 4) + col4] = o;
}

extern "C" void kernel_launch(void* const* d_in, const int* in_sizes, int n_in,
                              void* d_out, int out_size) {
    const float* pre  = (const float*)d_in[0];   // [T, NPRE]
    const float* post = (const float*)d_in[1];   // [T, NPOST]
    float* e = (float*)d_out;                    // [NPRE, NPOST]

    stdp_fused_kernel<<<NBLK, NTHR>>>(pre, post, e);
}

// round 12
// speedup vs baseline: 1.6650x; 1.6650x over previous
#include <cuda_runtime.h>

#define T_STEPS 256
#define NPRE    1024
#define NPOST   1024
#define K       16            // 2^-16 rel truncation; measured rel_err 3.2e-5, 30x under 1e-3

// Scratch vectors (no allocations allowed)
__device__ float g_x[NPRE];   // pre trace at T
__device__ float g_p[NPRE];   // pre[T-1][:]
__device__ float g_y[NPOST];  // post trace at T
__device__ float g_q[NPOST];  // post[T-1][:]

// Kernel A: closed-form traces, computed ONCE (no per-block redundancy).
// x[i] = sum_{k=0..K-1} pre[T-K+k][i] * 2^(k-K)   (TP=2 geometric filter)
__global__ void trace_kernel(const float* __restrict__ pre,
                             const float* __restrict__ post) {
    const int t     = blockIdx.x * blockDim.x + threadIdx.x;  // 0..2047
    const int which = t >> 10;                                // 0 = pre, 1 = post
    const int col   = t & 1023;

    const float* __restrict__ s = which ? post : pre;
    const float* __restrict__ b = s + (size_t)(T_STEPS - K) * NPRE + col;

    // 16 independent loads (MLP=16, single latency exposure), 2 acc chains
    float a0 = 0.0f, a1 = 0.0f, last = 0.0f;
    #pragma unroll
    for (int k = 0; k < K; k += 2) {
        const float v0 = b[(size_t)(k + 0) * NPRE];
        const float v1 = b[(size_t)(k + 1) * NPRE];
        a0 = fmaf(v0, __uint_as_float((unsigned)(127 - K + k + 0) << 23), a0);
        a1 = fmaf(v1, __uint_as_float((unsigned)(127 - K + k + 1) << 23), a1);
        last = v1;                                            // k+1 == K-1 survives
    }
    const float acc = a0 + a1;

    if (which) { g_y[col] = acc; g_q[col] = last; }
    else       { g_x[col] = acc; g_p[col] = last; }
}

// Kernel B: e[i][j] = x[i]*q[j] - p[i]*y[j].  No smem, no barrier, no redundancy.
// 256 blocks x 1024 threads; thread -> (row = blk*4 + tid>>8, cols 4*(tid&255)..+3)
__global__ void outer_kernel(float* __restrict__ e) {
    const int tid  = threadIdx.x;
    const int col4 = tid & 255;
    const int i    = blockIdx.x * 4 + (tid >> 8);

    const float xi = g_x[i];                                  // uniform per 256-thread group
    const float pi = g_p[i];
    const float4 y4 = reinterpret_cast<const float4*>(g_y)[col4];
    const float4 q4 = reinterpret_cast<const float4*>(g_q)[col4];

    float4 o;
    o.x = fmaf(xi, q4.x, -pi * y4.x);
    o.y = fmaf(xi, q4.y, -pi * y4.y);
    o.z = fmaf(xi, q4.z, -pi * y4.z);
    o.w = fmaf(xi, q4.w, -pi * y4.w);

    reinterpret_cast<float4*>(e)[(size_t)i * (NPOST / 4) + col4] = o;
}

extern "C" void kernel_launch(void* const* d_in, const int* in_sizes, int n_in,
                              void* d_out, int out_size) {
    const float* pre  = (const float*)d_in[0];   // [T, NPRE]
    const float* post = (const float*)d_in[1];   // [T, NPOST]
    float* e = (float*)d_out;                    // [NPRE, NPOST]

    trace_kernel<<<8, 256>>>(pre, post);         // same stream -> ordered before outer
    outer_kernel<<<NPRE / 4, 1024>>>(e);
}